// round 2
// baseline (speedup 1.0000x reference)
#include <cuda_runtime.h>
#include <math.h>

// ---------------- scratch (allocation-free: __device__ globals) ----------------
// g_fv: [16][512][64*64]  ch 0-255 = f, ch 256-511 = v
__device__ float g_fv[16ull * 512 * 64 * 64];
// g_out1: [16][256][64*64] clustered output before final 1x1 conv
__device__ float g_out1[16ull * 256 * 64 * 64];

// ---------------- generic 1x1-conv GEMM ----------------
// C[z][o][p] = sum_k Wrow(o)[k] * X[z][k][p] + bias(o)
// rows o < split use (Wa, ba); rows >= split use (Wb, bb) with offset o-split.
#define BM 64
#define BN 64
#define BK 32
#define TM 4
#define TN 4

__global__ __launch_bounds__(256) void gemm_conv(
    const float* __restrict__ Wa, const float* __restrict__ Wb,
    const float* __restrict__ ba, const float* __restrict__ bb,
    int split,
    const float* __restrict__ X, float* __restrict__ C,
    int O, int K, int P)
{
    __shared__ float As[BK][BM];
    __shared__ float Bs[BK][BN];

    const int z = blockIdx.z;
    X += (size_t)z * K * P;
    C += (size_t)z * O * P;
    const int m0blk = blockIdx.y * BM;
    const int n0blk = blockIdx.x * BN;
    const int tid = threadIdx.x;
    const int tm = tid >> 4;   // 0..15
    const int tn = tid & 15;   // 0..15

    float acc[TM][TN];
#pragma unroll
    for (int i = 0; i < TM; i++)
#pragma unroll
        for (int j = 0; j < TN; j++) acc[i][j] = 0.0f;

    for (int k0 = 0; k0 < K; k0 += BK) {
        // Load A tile: BM x BK = 512 float4, 2 per thread. Transposed store.
#pragma unroll
        for (int i = 0; i < 2; i++) {
            int f = tid + i * 256;
            int row = f >> 3;            // 8 float4 per row of 32
            int kk = (f & 7) << 2;
            int gr = m0blk + row;
            float4 val = make_float4(0.f, 0.f, 0.f, 0.f);
            if (gr < O) {
                const float* wp = (gr < split) ? (Wa + (size_t)gr * K)
                                               : (Wb + (size_t)(gr - split) * K);
                val = *reinterpret_cast<const float4*>(wp + k0 + kk);
            }
            As[kk + 0][row] = val.x;
            As[kk + 1][row] = val.y;
            As[kk + 2][row] = val.z;
            As[kk + 3][row] = val.w;
        }
        // Load B tile: BK x BN = 512 float4, 2 per thread.
#pragma unroll
        for (int i = 0; i < 2; i++) {
            int f = tid + i * 256;
            int row = f >> 4;            // 16 float4 per row of 64
            int nn = (f & 15) << 2;
            float4 val = *reinterpret_cast<const float4*>(
                X + (size_t)(k0 + row) * P + n0blk + nn);
            *reinterpret_cast<float4*>(&Bs[row][nn]) = val;
        }
        __syncthreads();

#pragma unroll
        for (int k = 0; k < BK; k++) {
            float a[TM], b[TN];
#pragma unroll
            for (int i = 0; i < TM; i++) a[i] = As[k][tm * TM + i];
#pragma unroll
            for (int j = 0; j < TN; j++) b[j] = Bs[k][tn * TN + j];
#pragma unroll
            for (int i = 0; i < TM; i++)
#pragma unroll
                for (int j = 0; j < TN; j++) acc[i][j] += a[i] * b[j];
        }
        __syncthreads();
    }

#pragma unroll
    for (int i = 0; i < TM; i++) {
        int gr = m0blk + tm * TM + i;
        if (gr >= O) continue;
        float bias = (gr < split) ? ba[gr] : bb[gr - split];
        float4 v;
        v.x = acc[i][0] + bias;
        v.y = acc[i][1] + bias;
        v.z = acc[i][2] + bias;
        v.w = acc[i][3] + bias;
        *reinterpret_cast<float4*>(C + (size_t)gr * P + n0blk + tn * TN) = v;
    }
}

// ---------------- cluster kernel: one 128-thread block per region ----------------
// region r = ((b*8 + e)*8 + f1)*8 + f2 ; region tile = rows f1*8..+7, cols f2*8..+7
// c = 32 channels, N = 64 points, M = 4 centers (2x2 pool of 4x4 blocks)
__global__ __launch_bounds__(128) void cluster_kernel(
    const float* __restrict__ fv, float* __restrict__ out1,
    const float* __restrict__ alpha_p, const float* __restrict__ beta_p)
{
    const int r  = blockIdx.x;
    const int f2 = r & 7;
    const int f1 = (r >> 3) & 7;
    const int e  = (r >> 6) & 7;
    const int b  = r >> 9;
    const float alpha = alpha_p[0];
    const float beta  = beta_p[0];

    __shared__ float fs[64][33];
    __shared__ float vs[64][33];
    __shared__ float cfn[4][32];   // normalized centers
    __shared__ float vcs[4][32];   // value centers
    __shared__ float aggs[4][32];
    __shared__ float pnorm_s[64];
    __shared__ float simv[64];
    __shared__ int   idxs[64];
    __shared__ float cnt[4];

    const int tid = threadIdx.x;

    const float* fb = fv + ((size_t)b * 512 + e * 32) * 4096 + (f1 * 8) * 64 + f2 * 8;
    const float* vb = fb + (size_t)256 * 4096;

    // load region: 2048 f + 2048 v elements (pt-major smem, padded)
    for (int i = tid; i < 2048; i += 128) {
        int ch = i >> 6;
        int pt = i & 63;
        int off = ch * 4096 + (pt >> 3) * 64 + (pt & 7);
        fs[pt][ch] = fb[off];
        vs[pt][ch] = vb[off];
    }
    if (tid < 4) cnt[tid] = 0.0f;
    __syncthreads();

    // centers: warp m handles center m, lane = channel
    {
        int m = tid >> 5;
        int c = tid & 31;
        int wy = (m >> 1) * 4;   // m = pw*2 + ph
        int hx = (m & 1) * 4;
        float cf = -INFINITY, cv = -INFINITY;
#pragma unroll
        for (int dy = 0; dy < 4; dy++)
#pragma unroll
            for (int dx = 0; dx < 4; dx++) {
                int pt = (wy + dy) * 8 + (hx + dx);
                cf = fmaxf(cf, fs[pt][c]);
                cv = fmaxf(cv, vs[pt][c]);
            }
        vcs[m][c] = cv;
        float sq = cf * cf;
#pragma unroll
        for (int o = 16; o > 0; o >>= 1) sq += __shfl_xor_sync(0xffffffffu, sq, o);
        float nrm = fmaxf(sqrtf(sq), 1e-12f);
        cfn[m][c] = cf / nrm;
    }
    // point norms
    if (tid < 64) {
        float sq = 0.0f;
#pragma unroll
        for (int c = 0; c < 32; c++) { float t = fs[tid][c]; sq += t * t; }
        pnorm_s[tid] = fmaxf(sqrtf(sq), 1e-12f);
    }
    __syncthreads();

    // per-point cos/sim/argmax (first-max tie-break == jnp.argmax)
    if (tid < 64) {
        int n = tid;
        float inv = 1.0f / pnorm_s[n];
        float best = -INFINITY;
        int bi = 0;
#pragma unroll
        for (int m = 0; m < 4; m++) {
            float dot = 0.0f;
#pragma unroll
            for (int c = 0; c < 32; c++) dot += cfn[m][c] * fs[n][c];
            float cosv = dot * inv;
            float s = 1.0f / (1.0f + expf(-(beta + alpha * cosv)));
            if (s > best) { best = s; bi = m; }
        }
        simv[n] = best;
        idxs[n] = bi;
        atomicAdd(&cnt[bi], 1.0f);
    }
    __syncthreads();

    // aggregate: thread (m = tid/32, c = tid%32)
    {
        int m = tid >> 5;
        int c = tid & 31;
        float s = vcs[m][c];
        for (int n = 0; n < 64; n++) {
            if (idxs[n] == m) s += vs[n][c] * simv[n];
        }
        aggs[m][c] = s / (cnt[m] + 1.0f);
    }
    __syncthreads();

    // dispatch: point n writes its 32 channels
    if (tid < 64) {
        int n = tid;
        int m = idxs[n];
        float s = simv[n];
        float* ob = out1 + ((size_t)b * 256 + e * 32) * 4096 + (f1 * 8) * 64 + f2 * 8;
        int off0 = (n >> 3) * 64 + (n & 7);
#pragma unroll
        for (int c = 0; c < 32; c++) {
            ob[c * 4096 + off0] = aggs[m][c] * s;
        }
    }
}

// ---------------- launch ----------------
extern "C" void kernel_launch(void* const* d_in, const int* in_sizes, int n_in,
                              void* d_out, int out_size)
{
    const float* x  = (const float*)d_in[0];   // [16,96,64,64]
    const float* Wf = (const float*)d_in[1];   // [256,96]
    const float* bf = (const float*)d_in[2];   // [256]
    const float* Wv = (const float*)d_in[3];   // [256,96]
    const float* bv = (const float*)d_in[4];   // [256]
    const float* Wp = (const float*)d_in[5];   // [96,256]
    const float* bp = (const float*)d_in[6];   // [96]
    const float* sa = (const float*)d_in[7];   // [1]
    const float* sb = (const float*)d_in[8];   // [1]
    float* out = (float*)d_out;                // [16,96,64,64]

    float* fv_ptr   = nullptr;
    float* out1_ptr = nullptr;
    cudaGetSymbolAddress((void**)&fv_ptr,   g_fv);
    cudaGetSymbolAddress((void**)&out1_ptr, g_out1);

    // 1) f & v convs fused in one GEMM over 512 output rows
    {
        dim3 grid(4096 / BN, 512 / BM, 16);
        gemm_conv<<<grid, 256>>>(Wf, Wv, bf, bv, 256, x, fv_ptr, 512, 96, 4096);
    }
    // 2) cluster stage: 16*8*64 = 8192 regions
    cluster_kernel<<<8192, 128>>>(fv_ptr, out1_ptr, sa, sb);
    // 3) final 1x1 conv (O=96 masked into 2 row-tiles)
    {
        dim3 grid(4096 / BN, (96 + BM - 1) / BM, 16);
        gemm_conv<<<grid, 256>>>(Wp, Wp, bp, bp, 96, out1_ptr, out, 96, 256, 4096);
    }
}

// round 4
// speedup vs baseline: 1.0886x; 1.0886x over previous
#include <cuda_runtime.h>
#include <math.h>

// ---------------- scratch (allocation-free: __device__ globals) ----------------
// g_fv: [16][512][64*64]  ch 0-255 = f, ch 256-511 = v
__device__ float g_fv[16ull * 512 * 64 * 64];
// g_out1: [16][256][64*64] clustered output before final 1x1 conv
__device__ float g_out1[16ull * 256 * 64 * 64];

// ---------------- 1x1-conv SGEMM: 128x128x16 tile, 8x8 microtile ----------------
// C[z][o][p] = sum_k Wrow(o)[k] * X[z][k][p] + bias(o)
// rows o < split use (Wa, ba); rows >= split use (Wb, bb) with offset o-split.
#define BM 128
#define BN 128
#define BKK 16
#define ASTRIDE 132   // padded row for As to reduce store conflicts

__global__ __launch_bounds__(256) void gemm_conv(
    const float* __restrict__ Wa, const float* __restrict__ Wb,
    const float* __restrict__ ba, const float* __restrict__ bb,
    int split,
    const float* __restrict__ X, float* __restrict__ C,
    int O, int K, int P)
{
    __shared__ float As[BKK][ASTRIDE];   // [k][m] transposed weights
    __shared__ float Bs[BKK][BN];        // [k][n]

    const int z = blockIdx.z;
    X += (size_t)z * K * P;
    C += (size_t)z * O * P;
    const int m0blk = blockIdx.y * BM;
    const int n0blk = blockIdx.x * BN;
    const int tid = threadIdx.x;
    const int tm = tid >> 4;   // 0..15
    const int tn = tid & 15;   // 0..15

    // A-tile load mapping: 128 rows x 16 k = 512 float4, 2 per thread
    const int a_row0 = tid >> 2;          // 0..63   (f = tid)
    const int a_kk   = (tid & 3) << 2;    // 0,4,8,12
    // second: f = tid + 256 -> row 64 + a_row0, same kk
    // B-tile load mapping: 16 rows x 128 n = 512 float4, 2 per thread
    const int b_row0 = tid >> 5;          // 0..7
    const int b_nn   = (tid & 31) << 2;   // 0..124
    // second: row 8 + b_row0

    float acc[8][8];
#pragma unroll
    for (int i = 0; i < 8; i++)
#pragma unroll
        for (int j = 0; j < 8; j++) acc[i][j] = 0.0f;

    float4 pA0, pA1, pB0, pB1;

    // helper lambdas (inlined manually)
    // ---- load stage k0=0 into regs ----
    {
        int gr0 = m0blk + a_row0;
        int gr1 = gr0 + 64;
        pA0 = make_float4(0.f,0.f,0.f,0.f);
        pA1 = make_float4(0.f,0.f,0.f,0.f);
        if (gr0 < O) {
            const float* wp = (gr0 < split) ? (Wa + (size_t)gr0 * K)
                                            : (Wb + (size_t)(gr0 - split) * K);
            pA0 = *reinterpret_cast<const float4*>(wp + a_kk);
        }
        if (gr1 < O) {
            const float* wp = (gr1 < split) ? (Wa + (size_t)gr1 * K)
                                            : (Wb + (size_t)(gr1 - split) * K);
            pA1 = *reinterpret_cast<const float4*>(wp + a_kk);
        }
        pB0 = *reinterpret_cast<const float4*>(X + (size_t)b_row0 * P + n0blk + b_nn);
        pB1 = *reinterpret_cast<const float4*>(X + (size_t)(b_row0 + 8) * P + n0blk + b_nn);
    }
    // store to smem
    As[a_kk + 0][a_row0] = pA0.x;
    As[a_kk + 1][a_row0] = pA0.y;
    As[a_kk + 2][a_row0] = pA0.z;
    As[a_kk + 3][a_row0] = pA0.w;
    As[a_kk + 0][a_row0 + 64] = pA1.x;
    As[a_kk + 1][a_row0 + 64] = pA1.y;
    As[a_kk + 2][a_row0 + 64] = pA1.z;
    As[a_kk + 3][a_row0 + 64] = pA1.w;
    *reinterpret_cast<float4*>(&Bs[b_row0][b_nn]) = pB0;
    *reinterpret_cast<float4*>(&Bs[b_row0 + 8][b_nn]) = pB1;
    __syncthreads();

    for (int k0 = BKK; ; k0 += BKK) {
        const bool last = (k0 >= K);
        if (!last) {
            int gr0 = m0blk + a_row0;
            int gr1 = gr0 + 64;
            pA0 = make_float4(0.f,0.f,0.f,0.f);
            pA1 = make_float4(0.f,0.f,0.f,0.f);
            if (gr0 < O) {
                const float* wp = (gr0 < split) ? (Wa + (size_t)gr0 * K)
                                                : (Wb + (size_t)(gr0 - split) * K);
                pA0 = *reinterpret_cast<const float4*>(wp + k0 + a_kk);
            }
            if (gr1 < O) {
                const float* wp = (gr1 < split) ? (Wa + (size_t)gr1 * K)
                                                : (Wb + (size_t)(gr1 - split) * K);
                pA1 = *reinterpret_cast<const float4*>(wp + k0 + a_kk);
            }
            pB0 = *reinterpret_cast<const float4*>(X + (size_t)(k0 + b_row0) * P + n0blk + b_nn);
            pB1 = *reinterpret_cast<const float4*>(X + (size_t)(k0 + b_row0 + 8) * P + n0blk + b_nn);
        }

        // ---- compute on current smem tiles ----
#pragma unroll
        for (int k = 0; k < BKK; k++) {
            float4 a0 = *reinterpret_cast<const float4*>(&As[k][tm * 4]);
            float4 a1 = *reinterpret_cast<const float4*>(&As[k][64 + tm * 4]);
            float4 b0 = *reinterpret_cast<const float4*>(&Bs[k][tn * 4]);
            float4 b1 = *reinterpret_cast<const float4*>(&Bs[k][64 + tn * 4]);
            float av[8] = {a0.x, a0.y, a0.z, a0.w, a1.x, a1.y, a1.z, a1.w};
            float bv[8] = {b0.x, b0.y, b0.z, b0.w, b1.x, b1.y, b1.z, b1.w};
#pragma unroll
            for (int i = 0; i < 8; i++)
#pragma unroll
                for (int j = 0; j < 8; j++) acc[i][j] += av[i] * bv[j];
        }

        if (last) break;
        __syncthreads();
        As[a_kk + 0][a_row0] = pA0.x;
        As[a_kk + 1][a_row0] = pA0.y;
        As[a_kk + 2][a_row0] = pA0.z;
        As[a_kk + 3][a_row0] = pA0.w;
        As[a_kk + 0][a_row0 + 64] = pA1.x;
        As[a_kk + 1][a_row0 + 64] = pA1.y;
        As[a_kk + 2][a_row0 + 64] = pA1.z;
        As[a_kk + 3][a_row0 + 64] = pA1.w;
        *reinterpret_cast<float4*>(&Bs[b_row0][b_nn]) = pB0;
        *reinterpret_cast<float4*>(&Bs[b_row0 + 8][b_nn]) = pB1;
        __syncthreads();
    }

    // ---- epilogue: bias + store (rows: tm*4+i and 64+tm*4+i; cols: tn*4, 64+tn*4)
#pragma unroll
    for (int half = 0; half < 2; half++) {
#pragma unroll
        for (int i = 0; i < 4; i++) {
            int gr = m0blk + half * 64 + tm * 4 + i;
            if (gr >= O) continue;
            float bias = (gr < split) ? ba[gr] : bb[gr - split];
            int ai = half * 4 + i;
            float4 v0, v1;
            v0.x = acc[ai][0] + bias; v0.y = acc[ai][1] + bias;
            v0.z = acc[ai][2] + bias; v0.w = acc[ai][3] + bias;
            v1.x = acc[ai][4] + bias; v1.y = acc[ai][5] + bias;
            v1.z = acc[ai][6] + bias; v1.w = acc[ai][7] + bias;
            *reinterpret_cast<float4*>(C + (size_t)gr * P + n0blk + tn * 4) = v0;
            *reinterpret_cast<float4*>(C + (size_t)gr * P + n0blk + 64 + tn * 4) = v1;
        }
    }
}

// ---------------- cluster kernel: one 128-thread block per region ----------------
// region r = ((b*8 + e)*8 + f1)*8 + f2 ; region tile = rows f1*8..+7, cols f2*8..+7
// c = 32 channels, N = 64 points, M = 4 centers (2x2 pool of 4x4 blocks)
__global__ __launch_bounds__(128) void cluster_kernel(
    const float* __restrict__ fv, float* __restrict__ out1,
    const float* __restrict__ alpha_p, const float* __restrict__ beta_p)
{
    const int r  = blockIdx.x;
    const int f2 = r & 7;
    const int f1 = (r >> 3) & 7;
    const int e  = (r >> 6) & 7;
    const int b  = r >> 9;
    const float alpha = alpha_p[0];
    const float beta  = beta_p[0];

    __shared__ float fs[64][33];
    __shared__ float vs[64][33];
    __shared__ float cfn[4][32];   // normalized centers
    __shared__ float vcs[4][32];   // value centers
    __shared__ float aggs[4][32];
    __shared__ float pnorm_s[64];
    __shared__ float simv[64];
    __shared__ int   idxs[64];
    __shared__ float cnt[4];

    const int tid = threadIdx.x;

    const float* fb = fv + ((size_t)b * 512 + e * 32) * 4096 + (f1 * 8) * 64 + f2 * 8;
    const float* vb = fb + (size_t)256 * 4096;

    // load region: 512 float4 for f, 512 for v (pt-major smem, padded)
    for (int i = tid; i < 512; i += 128) {
        int ch   = i >> 4;
        int rem  = i & 15;
        int row  = rem >> 1;
        int half = rem & 1;
        int off  = ch * 4096 + row * 64 + half * 4;
        float4 fval = *reinterpret_cast<const float4*>(fb + off);
        float4 vval = *reinterpret_cast<const float4*>(vb + off);
        int pt = row * 8 + half * 4;
        fs[pt + 0][ch] = fval.x; fs[pt + 1][ch] = fval.y;
        fs[pt + 2][ch] = fval.z; fs[pt + 3][ch] = fval.w;
        vs[pt + 0][ch] = vval.x; vs[pt + 1][ch] = vval.y;
        vs[pt + 2][ch] = vval.z; vs[pt + 3][ch] = vval.w;
    }
    if (tid < 4) cnt[tid] = 0.0f;
    __syncthreads();

    // centers: warp m handles center m, lane = channel
    {
        int m = tid >> 5;
        int c = tid & 31;
        int wy = (m >> 1) * 4;   // m = pw*2 + ph
        int hx = (m & 1) * 4;
        float cf = -INFINITY, cv = -INFINITY;
#pragma unroll
        for (int dy = 0; dy < 4; dy++)
#pragma unroll
            for (int dx = 0; dx < 4; dx++) {
                int pt = (wy + dy) * 8 + (hx + dx);
                cf = fmaxf(cf, fs[pt][c]);
                cv = fmaxf(cv, vs[pt][c]);
            }
        vcs[m][c] = cv;
        float sq = cf * cf;
#pragma unroll
        for (int o = 16; o > 0; o >>= 1) sq += __shfl_xor_sync(0xffffffffu, sq, o);
        float nrm = fmaxf(sqrtf(sq), 1e-12f);
        cfn[m][c] = cf / nrm;
    }
    // point norms
    if (tid < 64) {
        float sq = 0.0f;
#pragma unroll
        for (int c = 0; c < 32; c++) { float t = fs[tid][c]; sq += t * t; }
        pnorm_s[tid] = fmaxf(sqrtf(sq), 1e-12f);
    }
    __syncthreads();

    // per-point cos/sim/argmax (first-max tie-break == jnp.argmax)
    if (tid < 64) {
        int n = tid;
        float inv = 1.0f / pnorm_s[n];
        float best = -INFINITY;
        int bi = 0;
#pragma unroll
        for (int m = 0; m < 4; m++) {
            float dot = 0.0f;
#pragma unroll
            for (int c = 0; c < 32; c++) dot += cfn[m][c] * fs[n][c];
            float cosv = dot * inv;
            float s = 1.0f / (1.0f + expf(-(beta + alpha * cosv)));
            if (s > best) { best = s; bi = m; }
        }
        simv[n] = best;
        idxs[n] = bi;
        atomicAdd(&cnt[bi], 1.0f);
    }
    __syncthreads();

    // aggregate: thread (m = tid/32, c = tid%32)
    {
        int m = tid >> 5;
        int c = tid & 31;
        float s = vcs[m][c];
        for (int n = 0; n < 64; n++) {
            if (idxs[n] == m) s += vs[n][c] * simv[n];
        }
        aggs[m][c] = s / (cnt[m] + 1.0f);
    }
    __syncthreads();

    // dispatch: compute out values into fs (reuse), then coalesced float4 store
    if (tid < 64) {
        int n = tid;
        int m = idxs[n];
        float s = simv[n];
#pragma unroll
        for (int c = 0; c < 32; c++) fs[n][c] = aggs[m][c] * s;
    }
    __syncthreads();

    float* ob = out1 + ((size_t)b * 256 + e * 32) * 4096 + (f1 * 8) * 64 + f2 * 8;
    for (int i = tid; i < 512; i += 128) {
        int ch   = i >> 4;
        int rem  = i & 15;
        int row  = rem >> 1;
        int half = rem & 1;
        int pt = row * 8 + half * 4;
        float4 v;
        v.x = fs[pt + 0][ch];
        v.y = fs[pt + 1][ch];
        v.z = fs[pt + 2][ch];
        v.w = fs[pt + 3][ch];
        *reinterpret_cast<float4*>(ob + ch * 4096 + row * 64 + half * 4) = v;
    }
}

// ---------------- launch ----------------
extern "C" void kernel_launch(void* const* d_in, const int* in_sizes, int n_in,
                              void* d_out, int out_size)
{
    const float* x  = (const float*)d_in[0];   // [16,96,64,64]
    const float* Wf = (const float*)d_in[1];   // [256,96]
    const float* bf = (const float*)d_in[2];   // [256]
    const float* Wv = (const float*)d_in[3];   // [256,96]
    const float* bv = (const float*)d_in[4];   // [256]
    const float* Wp = (const float*)d_in[5];   // [96,256]
    const float* bp = (const float*)d_in[6];   // [96]
    const float* sa = (const float*)d_in[7];   // [1]
    const float* sb = (const float*)d_in[8];   // [1]
    float* out = (float*)d_out;                // [16,96,64,64]

    float* fv_ptr   = nullptr;
    float* out1_ptr = nullptr;
    cudaGetSymbolAddress((void**)&fv_ptr,   g_fv);
    cudaGetSymbolAddress((void**)&out1_ptr, g_out1);

    // 1) f & v convs fused in one GEMM over 512 output rows
    {
        dim3 grid(4096 / BN, 512 / BM, 16);
        gemm_conv<<<grid, 256>>>(Wf, Wv, bf, bv, 256, x, fv_ptr, 512, 96, 4096);
    }
    // 2) cluster stage: 16*8*64 = 8192 regions
    cluster_kernel<<<8192, 128>>>(fv_ptr, out1_ptr, sa, sb);
    // 3) final 1x1 conv (O=96, one masked row-tile)
    {
        dim3 grid(4096 / BN, (96 + BM - 1) / BM, 16);
        gemm_conv<<<grid, 256>>>(Wp, Wp, bp, bp, 96, out1_ptr, out, 96, 256, 4096);
    }
}

// round 6
// speedup vs baseline: 1.2589x; 1.1565x over previous
#include <cuda_runtime.h>
#include <math.h>

// ---------------- scratch (allocation-free: __device__ globals) ----------------
// g_fv: [16][512][64*64]  ch 0-255 = f, ch 256-511 = v
__device__ float g_fv[16ull * 512 * 64 * 64];
// g_out1: [16][256][64*64] clustered output before final 1x1 conv
__device__ float g_out1[16ull * 256 * 64 * 64];

// ---------------- 1x1-conv SGEMM: 64x128x16 tile, 8x8 microtile, 128 thr ----------------
// C[z][o][p] = sum_k Wrow(o)[k] * X[z][k][p] + bias(o)
// rows o < split use (Wa, ba); rows >= split use (Wb, bb) with offset o-split.
#define BM 64
#define BN 128
#define BKK 16
#define ASTRIDE 68   // padded row for As (multiple of 4 for float4 loads)

__global__ __launch_bounds__(128) void gemm_conv(
    const float* __restrict__ Wa, const float* __restrict__ Wb,
    const float* __restrict__ ba, const float* __restrict__ bb,
    int split,
    const float* __restrict__ X, float* __restrict__ C,
    int O, int K, int P)
{
    __shared__ float As[BKK][ASTRIDE];   // [k][m] transposed weights
    __shared__ float Bs[BKK][BN];        // [k][n]

    const int z = blockIdx.z;
    X += (size_t)z * K * P;
    C += (size_t)z * O * P;
    const int m0blk = blockIdx.y * BM;
    const int n0blk = blockIdx.x * BN;
    const int tid = threadIdx.x;
    const int tm = tid >> 4;   // 0..7
    const int tn = tid & 15;   // 0..15

    // A-tile load mapping: 64 rows x 16 k = 256 float4, 2 per thread.
    // row = tid&63 (warp-contiguous rows -> conflict-free transposed smem stores),
    // half = tid>>6 selects k-offset {0,8}.
    const int a_row = tid & 63;
    const int a_kk  = (tid >> 6) << 3;    // 0 or 8
    // B-tile load mapping: 16 rows x 128 n = 512 float4, 4 per thread
    const int b_row0 = tid >> 5;          // 0..3, then +4,+8,+12
    const int b_nn   = (tid & 31) << 2;   // 0..124

    float acc[8][8];
#pragma unroll
    for (int i = 0; i < 8; i++)
#pragma unroll
        for (int j = 0; j < 8; j++) acc[i][j] = 0.0f;

    float4 pA0, pA1, pB[4];

    const int gr_a = m0blk + a_row;
    const float* wp_a = nullptr;
    if (gr_a < O)
        wp_a = (gr_a < split) ? (Wa + (size_t)gr_a * K)
                              : (Wb + (size_t)(gr_a - split) * K);

    // ---- load stage k0=0 into regs ----
    pA0 = make_float4(0.f,0.f,0.f,0.f);
    pA1 = make_float4(0.f,0.f,0.f,0.f);
    if (wp_a) {
        pA0 = *reinterpret_cast<const float4*>(wp_a + a_kk);
        pA1 = *reinterpret_cast<const float4*>(wp_a + a_kk + 4);
    }
#pragma unroll
    for (int r = 0; r < 4; r++)
        pB[r] = *reinterpret_cast<const float4*>(
            X + (size_t)(b_row0 + r * 4) * P + n0blk + b_nn);

    // store to smem (transposed A)
    As[a_kk + 0][a_row] = pA0.x;
    As[a_kk + 1][a_row] = pA0.y;
    As[a_kk + 2][a_row] = pA0.z;
    As[a_kk + 3][a_row] = pA0.w;
    As[a_kk + 4][a_row] = pA1.x;
    As[a_kk + 5][a_row] = pA1.y;
    As[a_kk + 6][a_row] = pA1.z;
    As[a_kk + 7][a_row] = pA1.w;
#pragma unroll
    for (int r = 0; r < 4; r++)
        *reinterpret_cast<float4*>(&Bs[b_row0 + r * 4][b_nn]) = pB[r];
    __syncthreads();

    for (int k0 = BKK; ; k0 += BKK) {
        const bool last = (k0 >= K);
        if (!last) {
            pA0 = make_float4(0.f,0.f,0.f,0.f);
            pA1 = make_float4(0.f,0.f,0.f,0.f);
            if (wp_a) {
                pA0 = *reinterpret_cast<const float4*>(wp_a + k0 + a_kk);
                pA1 = *reinterpret_cast<const float4*>(wp_a + k0 + a_kk + 4);
            }
#pragma unroll
            for (int r = 0; r < 4; r++)
                pB[r] = *reinterpret_cast<const float4*>(
                    X + (size_t)(k0 + b_row0 + r * 4) * P + n0blk + b_nn);
        }

        // ---- compute on current smem tiles ----
#pragma unroll
        for (int k = 0; k < BKK; k++) {
            float4 a0 = *reinterpret_cast<const float4*>(&As[k][tm * 4]);
            float4 a1 = *reinterpret_cast<const float4*>(&As[k][32 + tm * 4]);
            float4 b0 = *reinterpret_cast<const float4*>(&Bs[k][tn * 4]);
            float4 b1 = *reinterpret_cast<const float4*>(&Bs[k][64 + tn * 4]);
            float av[8] = {a0.x, a0.y, a0.z, a0.w, a1.x, a1.y, a1.z, a1.w};
            float bv[8] = {b0.x, b0.y, b0.z, b0.w, b1.x, b1.y, b1.z, b1.w};
#pragma unroll
            for (int i = 0; i < 8; i++)
#pragma unroll
                for (int j = 0; j < 8; j++) acc[i][j] += av[i] * bv[j];
        }

        if (last) break;
        __syncthreads();
        As[a_kk + 0][a_row] = pA0.x;
        As[a_kk + 1][a_row] = pA0.y;
        As[a_kk + 2][a_row] = pA0.z;
        As[a_kk + 3][a_row] = pA0.w;
        As[a_kk + 4][a_row] = pA1.x;
        As[a_kk + 5][a_row] = pA1.y;
        As[a_kk + 6][a_row] = pA1.z;
        As[a_kk + 7][a_row] = pA1.w;
#pragma unroll
        for (int r = 0; r < 4; r++)
            *reinterpret_cast<float4*>(&Bs[b_row0 + r * 4][b_nn]) = pB[r];
        __syncthreads();
    }

    // ---- epilogue: bias + store (rows: half*32 + tm*4+i; cols: tn*4, 64+tn*4)
#pragma unroll
    for (int half = 0; half < 2; half++) {
#pragma unroll
        for (int i = 0; i < 4; i++) {
            int gr = m0blk + half * 32 + tm * 4 + i;
            if (gr >= O) continue;
            float bias = (gr < split) ? ba[gr] : bb[gr - split];
            int ai = half * 4 + i;
            float4 v0, v1;
            v0.x = acc[ai][0] + bias; v0.y = acc[ai][1] + bias;
            v0.z = acc[ai][2] + bias; v0.w = acc[ai][3] + bias;
            v1.x = acc[ai][4] + bias; v1.y = acc[ai][5] + bias;
            v1.z = acc[ai][6] + bias; v1.w = acc[ai][7] + bias;
            *reinterpret_cast<float4*>(C + (size_t)gr * P + n0blk + tn * 4) = v0;
            *reinterpret_cast<float4*>(C + (size_t)gr * P + n0blk + 64 + tn * 4) = v1;
        }
    }
}

// ---------------- cluster kernel: one 128-thread block per region ----------------
// region r = ((b*8 + e)*8 + f1)*8 + f2 ; region tile = rows f1*8..+7, cols f2*8..+7
// c = 32 channels, N = 64 points, M = 4 centers (2x2 pool of 4x4 blocks)
__global__ __launch_bounds__(128) void cluster_kernel(
    const float* __restrict__ fv, float* __restrict__ out1,
    const float* __restrict__ alpha_p, const float* __restrict__ beta_p)
{
    const int r  = blockIdx.x;
    const int f2 = r & 7;
    const int f1 = (r >> 3) & 7;
    const int e  = (r >> 6) & 7;
    const int b  = r >> 9;
    const float alpha = alpha_p[0];
    const float beta  = beta_p[0];

    __shared__ float fs[64][33];
    __shared__ float vs[64][33];
    __shared__ float cfn[4][32];   // normalized centers
    __shared__ float vcs[4][32];   // value centers
    __shared__ float aggs[4][32];
    __shared__ float pnorm_s[64];
    __shared__ float simv[64];
    __shared__ int   idxs[64];
    __shared__ float cnt[4];

    const int tid = threadIdx.x;

    const float* fb = fv + ((size_t)b * 512 + e * 32) * 4096 + (f1 * 8) * 64 + f2 * 8;
    const float* vb = fb + (size_t)256 * 4096;

    // load region: 512 float4 for f, 512 for v (pt-major smem, padded)
    for (int i = tid; i < 512; i += 128) {
        int ch   = i >> 4;
        int rem  = i & 15;
        int row  = rem >> 1;
        int half = rem & 1;
        int off  = ch * 4096 + row * 64 + half * 4;
        float4 fval = *reinterpret_cast<const float4*>(fb + off);
        float4 vval = *reinterpret_cast<const float4*>(vb + off);
        int pt = row * 8 + half * 4;
        fs[pt + 0][ch] = fval.x; fs[pt + 1][ch] = fval.y;
        fs[pt + 2][ch] = fval.z; fs[pt + 3][ch] = fval.w;
        vs[pt + 0][ch] = vval.x; vs[pt + 1][ch] = vval.y;
        vs[pt + 2][ch] = vval.z; vs[pt + 3][ch] = vval.w;
    }
    if (tid < 4) cnt[tid] = 0.0f;
    __syncthreads();

    // centers: warp m handles center m, lane = channel
    {
        int m = tid >> 5;
        int c = tid & 31;
        int wy = (m >> 1) * 4;   // m = pw*2 + ph
        int hx = (m & 1) * 4;
        float cf = -INFINITY, cv = -INFINITY;
#pragma unroll
        for (int dy = 0; dy < 4; dy++)
#pragma unroll
            for (int dx = 0; dx < 4; dx++) {
                int pt = (wy + dy) * 8 + (hx + dx);
                cf = fmaxf(cf, fs[pt][c]);
                cv = fmaxf(cv, vs[pt][c]);
            }
        vcs[m][c] = cv;
        float sq = cf * cf;
#pragma unroll
        for (int o = 16; o > 0; o >>= 1) sq += __shfl_xor_sync(0xffffffffu, sq, o);
        float nrm = fmaxf(sqrtf(sq), 1e-12f);
        cfn[m][c] = cf / nrm;
    }
    // point norms
    if (tid < 64) {
        float sq = 0.0f;
#pragma unroll
        for (int c = 0; c < 32; c++) { float t = fs[tid][c]; sq += t * t; }
        pnorm_s[tid] = fmaxf(sqrtf(sq), 1e-12f);
    }
    __syncthreads();

    // per-point cos/sim/argmax (first-max tie-break == jnp.argmax)
    if (tid < 64) {
        int n = tid;
        float inv = 1.0f / pnorm_s[n];
        float best = -INFINITY;
        int bi = 0;
#pragma unroll
        for (int m = 0; m < 4; m++) {
            float dot = 0.0f;
#pragma unroll
            for (int c = 0; c < 32; c++) dot += cfn[m][c] * fs[n][c];
            float cosv = dot * inv;
            float s = 1.0f / (1.0f + expf(-(beta + alpha * cosv)));
            if (s > best) { best = s; bi = m; }
        }
        simv[n] = best;
        idxs[n] = bi;
        atomicAdd(&cnt[bi], 1.0f);
    }
    __syncthreads();

    // aggregate: thread (m = tid/32, c = tid%32)
    {
        int m = tid >> 5;
        int c = tid & 31;
        float s = vcs[m][c];
        for (int n = 0; n < 64; n++) {
            if (idxs[n] == m) s += vs[n][c] * simv[n];
        }
        aggs[m][c] = s / (cnt[m] + 1.0f);
    }
    __syncthreads();

    // dispatch: compute out values into fs (reuse), then coalesced float4 store
    if (tid < 64) {
        int n = tid;
        int m = idxs[n];
        float s = simv[n];
#pragma unroll
        for (int c = 0; c < 32; c++) fs[n][c] = aggs[m][c] * s;
    }
    __syncthreads();

    float* ob = out1 + ((size_t)b * 256 + e * 32) * 4096 + (f1 * 8) * 64 + f2 * 8;
    for (int i = tid; i < 512; i += 128) {
        int ch   = i >> 4;
        int rem  = i & 15;
        int row  = rem >> 1;
        int half = rem & 1;
        int pt = row * 8 + half * 4;
        float4 v;
        v.x = fs[pt + 0][ch];
        v.y = fs[pt + 1][ch];
        v.z = fs[pt + 2][ch];
        v.w = fs[pt + 3][ch];
        *reinterpret_cast<float4*>(ob + ch * 4096 + row * 64 + half * 4) = v;
    }
}

// ---------------- launch ----------------
extern "C" void kernel_launch(void* const* d_in, const int* in_sizes, int n_in,
                              void* d_out, int out_size)
{
    const float* x  = (const float*)d_in[0];   // [16,96,64,64]
    const float* Wf = (const float*)d_in[1];   // [256,96]
    const float* bf = (const float*)d_in[2];   // [256]
    const float* Wv = (const float*)d_in[3];   // [256,96]
    const float* bv = (const float*)d_in[4];   // [256]
    const float* Wp = (const float*)d_in[5];   // [96,256]
    const float* bp = (const float*)d_in[6];   // [96]
    const float* sa = (const float*)d_in[7];   // [1]
    const float* sb = (const float*)d_in[8];   // [1]
    float* out = (float*)d_out;                // [16,96,64,64]

    float* fv_ptr   = nullptr;
    float* out1_ptr = nullptr;
    cudaGetSymbolAddress((void**)&fv_ptr,   g_fv);
    cudaGetSymbolAddress((void**)&out1_ptr, g_out1);

    // 1) f & v convs fused in one GEMM over 512 output rows
    {
        dim3 grid(4096 / BN, 512 / BM, 16);
        gemm_conv<<<grid, 128>>>(Wf, Wv, bf, bv, 256, x, fv_ptr, 512, 96, 4096);
    }
    // 2) cluster stage: 16*8*64 = 8192 regions
    cluster_kernel<<<8192, 128>>>(fv_ptr, out1_ptr, sa, sb);
    // 3) final 1x1 conv (O=96 -> 2 row-tiles of 64, second half-masked)
    {
        dim3 grid(4096 / BN, (96 + BM - 1) / BM, 16);
        gemm_conv<<<grid, 128>>>(Wp, Wp, bp, bp, 96, out1_ptr, out, 96, 256, 4096);
    }
}

// round 10
// speedup vs baseline: 1.4190x; 1.1272x over previous
#include <cuda_runtime.h>
#include <math.h>
#include <stdint.h>

// ---------------- scratch (allocation-free: __device__ globals) ----------------
// g_fv: [16][512][64*64]  ch 0-255 = f, ch 256-511 = v
__device__ float g_fv[16ull * 512 * 64 * 64];
// g_out1: [16][256][64*64] clustered output before final 1x1 conv
__device__ float g_out1[16ull * 256 * 64 * 64];

// ---------------- 1x1-conv SGEMM: 64x128x16 tile, 8x8 microtile, 128 thr ----------------
// Inner product uses packed fma.rn.f32x2 (FFMA2): 2 fp32 FMAs per issue slot.
// C[z][o][p] = sum_k Wrow(o)[k] * X[z][k][p] + bias(o)
// rows o < split use (Wa, ba); rows >= split use (Wb, bb) with offset o-split.
#define BM 64
#define BN 128
#define BKK 16
#define ASTRIDE 68   // padded row for As (multiple of 4 for float4 loads)

__global__ __launch_bounds__(128, 4) void gemm_conv(
    const float* __restrict__ Wa, const float* __restrict__ Wb,
    const float* __restrict__ ba, const float* __restrict__ bb,
    int split,
    const float* __restrict__ X, float* __restrict__ C,
    int O, int K, int P)
{
    __shared__ float As[BKK][ASTRIDE];   // [k][m] transposed weights
    __shared__ float Bs[BKK][BN];        // [k][n]

    const int z = blockIdx.z;
    X += (size_t)z * K * P;
    C += (size_t)z * O * P;
    const int m0blk = blockIdx.y * BM;
    const int n0blk = blockIdx.x * BN;
    const int tid = threadIdx.x;
    const int tm = tid >> 4;   // 0..7
    const int tn = tid & 15;   // 0..15

    // A-tile load mapping: 64 rows x 16 k = 256 float4, 2 per thread.
    const int a_row = tid & 63;
    const int a_kk  = (tid >> 6) << 3;    // 0 or 8
    // B-tile load mapping: 16 rows x 128 n = 512 float4, 4 per thread
    const int b_row0 = tid >> 5;          // 0..3, then +4,+8,+12
    const int b_nn   = (tid & 31) << 2;   // 0..124

    // packed accumulators: acc2[i][j] = pair of fp32 (cols 2j, 2j+1 of the 8-col frag)
    unsigned long long acc2[8][4];
#pragma unroll
    for (int i = 0; i < 8; i++)
#pragma unroll
        for (int j = 0; j < 4; j++) acc2[i][j] = 0ull;

    float4 pA0, pA1, pB[4];

    const int gr_a = m0blk + a_row;
    const float* wp_a = nullptr;
    if (gr_a < O)
        wp_a = (gr_a < split) ? (Wa + (size_t)gr_a * K)
                              : (Wb + (size_t)(gr_a - split) * K);

    // ---- load stage k0=0 into regs ----
    pA0 = make_float4(0.f,0.f,0.f,0.f);
    pA1 = make_float4(0.f,0.f,0.f,0.f);
    if (wp_a) {
        pA0 = *reinterpret_cast<const float4*>(wp_a + a_kk);
        pA1 = *reinterpret_cast<const float4*>(wp_a + a_kk + 4);
    }
#pragma unroll
    for (int r = 0; r < 4; r++)
        pB[r] = *reinterpret_cast<const float4*>(
            X + (size_t)(b_row0 + r * 4) * P + n0blk + b_nn);

    As[a_kk + 0][a_row] = pA0.x;
    As[a_kk + 1][a_row] = pA0.y;
    As[a_kk + 2][a_row] = pA0.z;
    As[a_kk + 3][a_row] = pA0.w;
    As[a_kk + 4][a_row] = pA1.x;
    As[a_kk + 5][a_row] = pA1.y;
    As[a_kk + 6][a_row] = pA1.z;
    As[a_kk + 7][a_row] = pA1.w;
#pragma unroll
    for (int r = 0; r < 4; r++)
        *reinterpret_cast<float4*>(&Bs[b_row0 + r * 4][b_nn]) = pB[r];
    __syncthreads();

    for (int k0 = BKK; ; k0 += BKK) {
        const bool last = (k0 >= K);
        if (!last) {
            pA0 = make_float4(0.f,0.f,0.f,0.f);
            pA1 = make_float4(0.f,0.f,0.f,0.f);
            if (wp_a) {
                pA0 = *reinterpret_cast<const float4*>(wp_a + k0 + a_kk);
                pA1 = *reinterpret_cast<const float4*>(wp_a + k0 + a_kk + 4);
            }
#pragma unroll
            for (int r = 0; r < 4; r++)
                pB[r] = *reinterpret_cast<const float4*>(
                    X + (size_t)(k0 + b_row0 + r * 4) * P + n0blk + b_nn);
        }

        // ---- compute on current smem tiles (packed f32x2 FMA) ----
#pragma unroll
        for (int k = 0; k < BKK; k++) {
            float4 a0 = *reinterpret_cast<const float4*>(&As[k][tm * 4]);
            float4 a1 = *reinterpret_cast<const float4*>(&As[k][32 + tm * 4]);
            // b fragment as packed fp32 pairs straight from shared (16B aligned)
            ulonglong2 bq0 = *reinterpret_cast<const ulonglong2*>(&Bs[k][tn * 4]);
            ulonglong2 bq1 = *reinterpret_cast<const ulonglong2*>(&Bs[k][64 + tn * 4]);
            unsigned long long bb4[4] = {bq0.x, bq0.y, bq1.x, bq1.y};
            float av[8] = {a0.x, a0.y, a0.z, a0.w, a1.x, a1.y, a1.z, a1.w};
#pragma unroll
            for (int i = 0; i < 8; i++) {
                unsigned long long aa;
                asm("mov.b64 %0, {%1, %1};" : "=l"(aa) : "r"(__float_as_uint(av[i])));
#pragma unroll
                for (int j = 0; j < 4; j++) {
                    asm("fma.rn.f32x2 %0, %1, %2, %0;"
                        : "+l"(acc2[i][j]) : "l"(aa), "l"(bb4[j]));
                }
            }
        }

        if (last) break;
        __syncthreads();
        As[a_kk + 0][a_row] = pA0.x;
        As[a_kk + 1][a_row] = pA0.y;
        As[a_kk + 2][a_row] = pA0.z;
        As[a_kk + 3][a_row] = pA0.w;
        As[a_kk + 4][a_row] = pA1.x;
        As[a_kk + 5][a_row] = pA1.y;
        As[a_kk + 6][a_row] = pA1.z;
        As[a_kk + 7][a_row] = pA1.w;
#pragma unroll
        for (int r = 0; r < 4; r++)
            *reinterpret_cast<float4*>(&Bs[b_row0 + r * 4][b_nn]) = pB[r];
        __syncthreads();
    }

    // ---- epilogue: unpack pairs, bias + store ----
#pragma unroll
    for (int half = 0; half < 2; half++) {
#pragma unroll
        for (int i = 0; i < 4; i++) {
            int gr = m0blk + half * 32 + tm * 4 + i;
            if (gr >= O) continue;
            float bias = (gr < split) ? ba[gr] : bb[gr - split];
            int ai = half * 4 + i;
            float c[8];
#pragma unroll
            for (int j = 0; j < 4; j++) {
                uint32_t lo, hi;
                asm("mov.b64 {%0, %1}, %2;" : "=r"(lo), "=r"(hi) : "l"(acc2[ai][j]));
                c[j * 2 + 0] = __uint_as_float(lo);
                c[j * 2 + 1] = __uint_as_float(hi);
            }
            float4 v0, v1;
            v0.x = c[0] + bias; v0.y = c[1] + bias;
            v0.z = c[2] + bias; v0.w = c[3] + bias;
            v1.x = c[4] + bias; v1.y = c[5] + bias;
            v1.z = c[6] + bias; v1.w = c[7] + bias;
            *reinterpret_cast<float4*>(C + (size_t)gr * P + n0blk + tn * 4) = v0;
            *reinterpret_cast<float4*>(C + (size_t)gr * P + n0blk + 64 + tn * 4) = v1;
        }
    }
}

// ---------------- cluster kernel: one 128-thread block per region ----------------
// region r = ((b*8 + e)*8 + f1)*8 + f2 ; region tile = rows f1*8..+7, cols f2*8..+7
// c = 32 channels, N = 64 points, M = 4 centers (2x2 pool of 4x4 blocks)
__global__ __launch_bounds__(128) void cluster_kernel(
    const float* __restrict__ fv, float* __restrict__ out1,
    const float* __restrict__ alpha_p, const float* __restrict__ beta_p)
{
    const int r  = blockIdx.x;
    const int f2 = r & 7;
    const int f1 = (r >> 3) & 7;
    const int e  = (r >> 6) & 7;
    const int b  = r >> 9;
    const float alpha = alpha_p[0];
    const float beta  = beta_p[0];

    __shared__ float fs[64][33];
    __shared__ float vs[64][33];
    __shared__ float cfn[4][32];   // normalized centers
    __shared__ float vcs[4][32];   // value centers
    __shared__ float aggs[4][32];
    __shared__ float pnorm_s[64];
    __shared__ float simv[64];
    __shared__ int   idxs[64];
    __shared__ float cnt[4];

    const int tid = threadIdx.x;

    const float* fb = fv + ((size_t)b * 512 + e * 32) * 4096 + (f1 * 8) * 64 + f2 * 8;
    const float* vb = fb + (size_t)256 * 4096;

    // load region: 512 float4 for f, 512 for v (pt-major smem, padded)
    for (int i = tid; i < 512; i += 128) {
        int ch   = i >> 4;
        int rem  = i & 15;
        int row  = rem >> 1;
        int half = rem & 1;
        int off  = ch * 4096 + row * 64 + half * 4;
        float4 fval = *reinterpret_cast<const float4*>(fb + off);
        float4 vval = *reinterpret_cast<const float4*>(vb + off);
        int pt = row * 8 + half * 4;
        fs[pt + 0][ch] = fval.x; fs[pt + 1][ch] = fval.y;
        fs[pt + 2][ch] = fval.z; fs[pt + 3][ch] = fval.w;
        vs[pt + 0][ch] = vval.x; vs[pt + 1][ch] = vval.y;
        vs[pt + 2][ch] = vval.z; vs[pt + 3][ch] = vval.w;
    }
    if (tid < 4) cnt[tid] = 0.0f;
    __syncthreads();

    // centers: warp m handles center m, lane = channel
    {
        int m = tid >> 5;
        int c = tid & 31;
        int wy = (m >> 1) * 4;   // m = pw*2 + ph
        int hx = (m & 1) * 4;
        float cf = -INFINITY, cv = -INFINITY;
#pragma unroll
        for (int dy = 0; dy < 4; dy++)
#pragma unroll
            for (int dx = 0; dx < 4; dx++) {
                int pt = (wy + dy) * 8 + (hx + dx);
                cf = fmaxf(cf, fs[pt][c]);
                cv = fmaxf(cv, vs[pt][c]);
            }
        vcs[m][c] = cv;
        float sq = cf * cf;
#pragma unroll
        for (int o = 16; o > 0; o >>= 1) sq += __shfl_xor_sync(0xffffffffu, sq, o);
        float nrm = fmaxf(sqrtf(sq), 1e-12f);
        cfn[m][c] = cf / nrm;
    }
    // point norms
    if (tid < 64) {
        float sq = 0.0f;
#pragma unroll
        for (int c = 0; c < 32; c++) { float t = fs[tid][c]; sq += t * t; }
        pnorm_s[tid] = fmaxf(sqrtf(sq), 1e-12f);
    }
    __syncthreads();

    // per-point cos/sim/argmax (first-max tie-break == jnp.argmax)
    if (tid < 64) {
        int n = tid;
        float inv = 1.0f / pnorm_s[n];
        float best = -INFINITY;
        int bi = 0;
#pragma unroll
        for (int m = 0; m < 4; m++) {
            float dot = 0.0f;
#pragma unroll
            for (int c = 0; c < 32; c++) dot += cfn[m][c] * fs[n][c];
            float cosv = dot * inv;
            float s = 1.0f / (1.0f + expf(-(beta + alpha * cosv)));
            if (s > best) { best = s; bi = m; }
        }
        simv[n] = best;
        idxs[n] = bi;
        atomicAdd(&cnt[bi], 1.0f);
    }
    __syncthreads();

    // aggregate: thread (m = tid/32, c = tid%32)
    {
        int m = tid >> 5;
        int c = tid & 31;
        float s = vcs[m][c];
        for (int n = 0; n < 64; n++) {
            if (idxs[n] == m) s += vs[n][c] * simv[n];
        }
        aggs[m][c] = s / (cnt[m] + 1.0f);
    }
    __syncthreads();

    // dispatch: compute out values into fs (reuse), then coalesced float4 store
    if (tid < 64) {
        int n = tid;
        int m = idxs[n];
        float s = simv[n];
#pragma unroll
        for (int c = 0; c < 32; c++) fs[n][c] = aggs[m][c] * s;
    }
    __syncthreads();

    float* ob = out1 + ((size_t)b * 256 + e * 32) * 4096 + (f1 * 8) * 64 + f2 * 8;
    for (int i = tid; i < 512; i += 128) {
        int ch   = i >> 4;
        int rem  = i & 15;
        int row  = rem >> 1;
        int half = rem & 1;
        int pt = row * 8 + half * 4;
        float4 v;
        v.x = fs[pt + 0][ch];
        v.y = fs[pt + 1][ch];
        v.z = fs[pt + 2][ch];
        v.w = fs[pt + 3][ch];
        *reinterpret_cast<float4*>(ob + ch * 4096 + row * 64 + half * 4) = v;
    }
}

// ---------------- launch ----------------
extern "C" void kernel_launch(void* const* d_in, const int* in_sizes, int n_in,
                              void* d_out, int out_size)
{
    const float* x  = (const float*)d_in[0];   // [16,96,64,64]
    const float* Wf = (const float*)d_in[1];   // [256,96]
    const float* bf = (const float*)d_in[2];   // [256]
    const float* Wv = (const float*)d_in[3];   // [256,96]
    const float* bv = (const float*)d_in[4];   // [256]
    const float* Wp = (const float*)d_in[5];   // [96,256]
    const float* bp = (const float*)d_in[6];   // [96]
    const float* sa = (const float*)d_in[7];   // [1]
    const float* sb = (const float*)d_in[8];   // [1]
    float* out = (float*)d_out;                // [16,96,64,64]

    float* fv_ptr   = nullptr;
    float* out1_ptr = nullptr;
    cudaGetSymbolAddress((void**)&fv_ptr,   g_fv);
    cudaGetSymbolAddress((void**)&out1_ptr, g_out1);

    // 1) f & v convs fused in one GEMM over 512 output rows
    {
        dim3 grid(4096 / BN, 512 / BM, 16);
        gemm_conv<<<grid, 128>>>(Wf, Wv, bf, bv, 256, x, fv_ptr, 512, 96, 4096);
    }
    // 2) cluster stage: 16*8*64 = 8192 regions
    cluster_kernel<<<8192, 128>>>(fv_ptr, out1_ptr, sa, sb);
    // 3) final 1x1 conv (O=96 -> 2 row-tiles of 64, second half-masked)
    {
        dim3 grid(4096 / BN, (96 + BM - 1) / BM, 16);
        gemm_conv<<<grid, 128>>>(Wp, Wp, bp, bp, 96, out1_ptr, out, 96, 256, 4096);
    }
}

// round 11
// speedup vs baseline: 1.4779x; 1.0415x over previous
#include <cuda_runtime.h>
#include <math.h>
#include <stdint.h>

// ---------------- scratch (allocation-free: __device__ globals) ----------------
// g_fv: [16][512][64*64]  ch 0-255 = f, ch 256-511 = v
__device__ float g_fv[16ull * 512 * 64 * 64];
// g_out1: [16][256][64*64] clustered output before final 1x1 conv
__device__ float g_out1[16ull * 256 * 64 * 64];

// ---------------- 1x1-conv SGEMM: 64x128x16 tile, 8x8 microtile, 128 thr ----------------
// Packed fma.rn.f32x2 inner product; double-buffered smem (1 sync per k-chunk);
// NI=4 template path skips dead upper-half rows (GEMM3 tail tile).
#define BM 64
#define BN 128
#define BKK 16
#define ASTRIDE 68

template<int NI>
__device__ __forceinline__ void compute_chunk(
    const float* __restrict__ As_, const float* __restrict__ Bs_,
    int tm, int tn, unsigned long long (*acc2)[4])
{
#pragma unroll
    for (int k = 0; k < BKK; k++) {
        const float* ak = As_ + k * ASTRIDE;
        const float* bk = Bs_ + k * BN;
        float4 a0 = *reinterpret_cast<const float4*>(ak + tm * 4);
        ulonglong2 bq0 = *reinterpret_cast<const ulonglong2*>(bk + tn * 4);
        ulonglong2 bq1 = *reinterpret_cast<const ulonglong2*>(bk + 64 + tn * 4);
        unsigned long long bb4[4] = {bq0.x, bq0.y, bq1.x, bq1.y};
        float av[8];
        av[0] = a0.x; av[1] = a0.y; av[2] = a0.z; av[3] = a0.w;
        if (NI == 8) {
            float4 a1 = *reinterpret_cast<const float4*>(ak + 32 + tm * 4);
            av[4] = a1.x; av[5] = a1.y; av[6] = a1.z; av[7] = a1.w;
        }
#pragma unroll
        for (int i = 0; i < NI; i++) {
            unsigned long long aa;
            asm("mov.b64 %0, {%1, %1};" : "=l"(aa) : "r"(__float_as_uint(av[i])));
#pragma unroll
            for (int j = 0; j < 4; j++) {
                asm("fma.rn.f32x2 %0, %1, %2, %0;"
                    : "+l"(acc2[i][j]) : "l"(aa), "l"(bb4[j]));
            }
        }
    }
}

__global__ __launch_bounds__(128, 4) void gemm_conv(
    const float* __restrict__ Wa, const float* __restrict__ Wb,
    const float* __restrict__ ba, const float* __restrict__ bb,
    int split,
    const float* __restrict__ X, float* __restrict__ C,
    int O, int K, int P)
{
    __shared__ float As[2][BKK * ASTRIDE];
    __shared__ float Bs[2][BKK * BN];

    const int z = blockIdx.z;
    X += (size_t)z * K * P;
    C += (size_t)z * O * P;
    const int m0blk = blockIdx.y * BM;
    const int n0blk = blockIdx.x * BN;
    const int tid = threadIdx.x;
    const int tm = tid >> 4;   // 0..7
    const int tn = tid & 15;   // 0..15

    // A-tile: 64 rows x 16 k = 256 float4, 2 per thread (transposed store)
    const int a_row = tid & 63;
    const int a_kk  = (tid >> 6) << 3;    // 0 or 8
    // B-tile: 16 rows x 128 n = 512 float4, 4 per thread
    const int b_row0 = tid >> 5;          // 0..3 (+4,+8,+12)
    const int b_nn   = (tid & 31) << 2;   // 0..124

    // skip upper-half rows entirely if all dead (GEMM3 tail tile)
    const bool full_rows = (m0blk + 32 < O) || (O >= m0blk + BM);

    unsigned long long acc2[8][4];
#pragma unroll
    for (int i = 0; i < 8; i++)
#pragma unroll
        for (int j = 0; j < 4; j++) acc2[i][j] = 0ull;

    float4 pA0, pA1, pB[4];

    const int gr_a = m0blk + a_row;
    const float* wp_a = nullptr;
    if (gr_a < O)
        wp_a = (gr_a < split) ? (Wa + (size_t)gr_a * K)
                              : (Wb + (size_t)(gr_a - split) * K);

    // ---- prologue: load chunk 0 and store into buffer 0 ----
    pA0 = make_float4(0.f,0.f,0.f,0.f);
    pA1 = make_float4(0.f,0.f,0.f,0.f);
    if (wp_a) {
        pA0 = *reinterpret_cast<const float4*>(wp_a + a_kk);
        pA1 = *reinterpret_cast<const float4*>(wp_a + a_kk + 4);
    }
#pragma unroll
    for (int r = 0; r < 4; r++)
        pB[r] = *reinterpret_cast<const float4*>(
            X + (size_t)(b_row0 + r * 4) * P + n0blk + b_nn);

    {
        float* as = As[0];
        as[(a_kk + 0) * ASTRIDE + a_row] = pA0.x;
        as[(a_kk + 1) * ASTRIDE + a_row] = pA0.y;
        as[(a_kk + 2) * ASTRIDE + a_row] = pA0.z;
        as[(a_kk + 3) * ASTRIDE + a_row] = pA0.w;
        as[(a_kk + 4) * ASTRIDE + a_row] = pA1.x;
        as[(a_kk + 5) * ASTRIDE + a_row] = pA1.y;
        as[(a_kk + 6) * ASTRIDE + a_row] = pA1.z;
        as[(a_kk + 7) * ASTRIDE + a_row] = pA1.w;
#pragma unroll
        for (int r = 0; r < 4; r++)
            *reinterpret_cast<float4*>(&Bs[0][(b_row0 + r * 4) * BN + b_nn]) = pB[r];
    }
    __syncthreads();

    int cur = 0;
    for (int k0 = BKK; ; k0 += BKK) {
        const bool last = (k0 >= K);
        if (!last) {
            pA0 = make_float4(0.f,0.f,0.f,0.f);
            pA1 = make_float4(0.f,0.f,0.f,0.f);
            if (wp_a) {
                pA0 = *reinterpret_cast<const float4*>(wp_a + k0 + a_kk);
                pA1 = *reinterpret_cast<const float4*>(wp_a + k0 + a_kk + 4);
            }
#pragma unroll
            for (int r = 0; r < 4; r++)
                pB[r] = *reinterpret_cast<const float4*>(
                    X + (size_t)(k0 + b_row0 + r * 4) * P + n0blk + b_nn);
        }

        if (full_rows) compute_chunk<8>(As[cur], Bs[cur], tm, tn, acc2);
        else           compute_chunk<4>(As[cur], Bs[cur], tm, tn, acc2);

        if (last) break;

        // store next chunk into the other buffer (no race: distinct buffer)
        {
            float* as = As[cur ^ 1];
            as[(a_kk + 0) * ASTRIDE + a_row] = pA0.x;
            as[(a_kk + 1) * ASTRIDE + a_row] = pA0.y;
            as[(a_kk + 2) * ASTRIDE + a_row] = pA0.z;
            as[(a_kk + 3) * ASTRIDE + a_row] = pA0.w;
            as[(a_kk + 4) * ASTRIDE + a_row] = pA1.x;
            as[(a_kk + 5) * ASTRIDE + a_row] = pA1.y;
            as[(a_kk + 6) * ASTRIDE + a_row] = pA1.z;
            as[(a_kk + 7) * ASTRIDE + a_row] = pA1.w;
#pragma unroll
            for (int r = 0; r < 4; r++)
                *reinterpret_cast<float4*>(&Bs[cur ^ 1][(b_row0 + r * 4) * BN + b_nn]) = pB[r];
        }
        __syncthreads();
        cur ^= 1;
    }

    // ---- epilogue: unpack pairs, bias + store ----
#pragma unroll
    for (int half = 0; half < 2; half++) {
#pragma unroll
        for (int i = 0; i < 4; i++) {
            int gr = m0blk + half * 32 + tm * 4 + i;
            if (gr >= O) continue;
            float bias = (gr < split) ? ba[gr] : bb[gr - split];
            int ai = half * 4 + i;
            float c[8];
#pragma unroll
            for (int j = 0; j < 4; j++) {
                uint32_t lo, hi;
                asm("mov.b64 {%0, %1}, %2;" : "=r"(lo), "=r"(hi) : "l"(acc2[ai][j]));
                c[j * 2 + 0] = __uint_as_float(lo);
                c[j * 2 + 1] = __uint_as_float(hi);
            }
            float4 v0, v1;
            v0.x = c[0] + bias; v0.y = c[1] + bias;
            v0.z = c[2] + bias; v0.w = c[3] + bias;
            v1.x = c[4] + bias; v1.y = c[5] + bias;
            v1.z = c[6] + bias; v1.w = c[7] + bias;
            *reinterpret_cast<float4*>(C + (size_t)gr * P + n0blk + tn * 4) = v0;
            *reinterpret_cast<float4*>(C + (size_t)gr * P + n0blk + 64 + tn * 4) = v1;
        }
    }
}

// ---------------- cluster kernel: one 128-thread block per region ----------------
__global__ __launch_bounds__(128) void cluster_kernel(
    const float* __restrict__ fv, float* __restrict__ out1,
    const float* __restrict__ alpha_p, const float* __restrict__ beta_p)
{
    const int r  = blockIdx.x;
    const int f2 = r & 7;
    const int f1 = (r >> 3) & 7;
    const int e  = (r >> 6) & 7;
    const int b  = r >> 9;
    const float alpha = alpha_p[0];
    const float beta  = beta_p[0];

    __shared__ float fs[64][33];
    __shared__ float vs[64][33];
    __shared__ float cfn[4][32];
    __shared__ float vcs[4][32];
    __shared__ float aggs[4][32];
    __shared__ float pnorm_s[64];
    __shared__ float simv[64];
    __shared__ int   idxs[64];
    __shared__ float cnt[4];

    const int tid = threadIdx.x;

    const float* fb = fv + ((size_t)b * 512 + e * 32) * 4096 + (f1 * 8) * 64 + f2 * 8;
    const float* vb = fb + (size_t)256 * 4096;

    for (int i = tid; i < 512; i += 128) {
        int ch   = i >> 4;
        int rem  = i & 15;
        int row  = rem >> 1;
        int half = rem & 1;
        int off  = ch * 4096 + row * 64 + half * 4;
        float4 fval = *reinterpret_cast<const float4*>(fb + off);
        float4 vval = *reinterpret_cast<const float4*>(vb + off);
        int pt = row * 8 + half * 4;
        fs[pt + 0][ch] = fval.x; fs[pt + 1][ch] = fval.y;
        fs[pt + 2][ch] = fval.z; fs[pt + 3][ch] = fval.w;
        vs[pt + 0][ch] = vval.x; vs[pt + 1][ch] = vval.y;
        vs[pt + 2][ch] = vval.z; vs[pt + 3][ch] = vval.w;
    }
    if (tid < 4) cnt[tid] = 0.0f;
    __syncthreads();

    {
        int m = tid >> 5;
        int c = tid & 31;
        int wy = (m >> 1) * 4;
        int hx = (m & 1) * 4;
        float cf = -INFINITY, cv = -INFINITY;
#pragma unroll
        for (int dy = 0; dy < 4; dy++)
#pragma unroll
            for (int dx = 0; dx < 4; dx++) {
                int pt = (wy + dy) * 8 + (hx + dx);
                cf = fmaxf(cf, fs[pt][c]);
                cv = fmaxf(cv, vs[pt][c]);
            }
        vcs[m][c] = cv;
        float sq = cf * cf;
#pragma unroll
        for (int o = 16; o > 0; o >>= 1) sq += __shfl_xor_sync(0xffffffffu, sq, o);
        float nrm = fmaxf(sqrtf(sq), 1e-12f);
        cfn[m][c] = cf / nrm;
    }
    if (tid < 64) {
        float sq = 0.0f;
#pragma unroll
        for (int c = 0; c < 32; c++) { float t = fs[tid][c]; sq += t * t; }
        pnorm_s[tid] = fmaxf(sqrtf(sq), 1e-12f);
    }
    __syncthreads();

    if (tid < 64) {
        int n = tid;
        float inv = 1.0f / pnorm_s[n];
        float best = -INFINITY;
        int bi = 0;
#pragma unroll
        for (int m = 0; m < 4; m++) {
            float dot = 0.0f;
#pragma unroll
            for (int c = 0; c < 32; c++) dot += cfn[m][c] * fs[n][c];
            float cosv = dot * inv;
            float s = 1.0f / (1.0f + expf(-(beta + alpha * cosv)));
            if (s > best) { best = s; bi = m; }
        }
        simv[n] = best;
        idxs[n] = bi;
        atomicAdd(&cnt[bi], 1.0f);
    }
    __syncthreads();

    {
        int m = tid >> 5;
        int c = tid & 31;
        float s = vcs[m][c];
        for (int n = 0; n < 64; n++) {
            if (idxs[n] == m) s += vs[n][c] * simv[n];
        }
        aggs[m][c] = s / (cnt[m] + 1.0f);
    }
    __syncthreads();

    if (tid < 64) {
        int n = tid;
        int m = idxs[n];
        float s = simv[n];
#pragma unroll
        for (int c = 0; c < 32; c++) fs[n][c] = aggs[m][c] * s;
    }
    __syncthreads();

    float* ob = out1 + ((size_t)b * 256 + e * 32) * 4096 + (f1 * 8) * 64 + f2 * 8;
    for (int i = tid; i < 512; i += 128) {
        int ch   = i >> 4;
        int rem  = i & 15;
        int row  = rem >> 1;
        int half = rem & 1;
        int pt = row * 8 + half * 4;
        float4 v;
        v.x = fs[pt + 0][ch];
        v.y = fs[pt + 1][ch];
        v.z = fs[pt + 2][ch];
        v.w = fs[pt + 3][ch];
        *reinterpret_cast<float4*>(ob + ch * 4096 + row * 64 + half * 4) = v;
    }
}

// ---------------- launch ----------------
extern "C" void kernel_launch(void* const* d_in, const int* in_sizes, int n_in,
                              void* d_out, int out_size)
{
    const float* x  = (const float*)d_in[0];   // [16,96,64,64]
    const float* Wf = (const float*)d_in[1];   // [256,96]
    const float* bf = (const float*)d_in[2];   // [256]
    const float* Wv = (const float*)d_in[3];   // [256,96]
    const float* bv = (const float*)d_in[4];   // [256]
    const float* Wp = (const float*)d_in[5];   // [96,256]
    const float* bp = (const float*)d_in[6];   // [96]
    const float* sa = (const float*)d_in[7];   // [1]
    const float* sb = (const float*)d_in[8];   // [1]
    float* out = (float*)d_out;                // [16,96,64,64]

    float* fv_ptr   = nullptr;
    float* out1_ptr = nullptr;
    cudaGetSymbolAddress((void**)&fv_ptr,   g_fv);
    cudaGetSymbolAddress((void**)&out1_ptr, g_out1);

    // 1) f & v convs fused in one GEMM over 512 output rows
    {
        dim3 grid(4096 / BN, 512 / BM, 16);
        gemm_conv<<<grid, 128>>>(Wf, Wv, bf, bv, 256, x, fv_ptr, 512, 96, 4096);
    }
    // 2) cluster stage: 16*8*64 = 8192 regions
    cluster_kernel<<<8192, 128>>>(fv_ptr, out1_ptr, sa, sb);
    // 3) final 1x1 conv (O=96 -> tile0 full, tile1 skips dead upper half)
    {
        dim3 grid(4096 / BN, (96 + BM - 1) / BM, 16);
        gemm_conv<<<grid, 128>>>(Wp, Wp, bp, bp, 96, out1_ptr, out, 96, 256, 4096);
    }
}

// round 12
// speedup vs baseline: 1.5656x; 1.0593x over previous
#include <cuda_runtime.h>
#include <math.h>
#include <stdint.h>

// ---------------- scratch (allocation-free: __device__ globals) ----------------
__device__ float g_fv[16ull * 512 * 64 * 64];    // f(0-255)+v(256-511)
__device__ float g_out1[16ull * 256 * 64 * 64];  // clustered output
__device__ float g_wt1[96 * 512];                // Wt1[k][o]: transposed Wf||Wv
__device__ float g_wt3[256 * 128];               // Wt3[k][o]: transposed Wp, o padded to 128
__device__ float g_b1[512];                      // bf || bv

#define BM 64
#define BN 128
#define BKK 16

// ---------------- prep: weight transpose + bias concat ----------------
__global__ __launch_bounds__(256) void prep_weights(
    const float* __restrict__ Wf, const float* __restrict__ bf,
    const float* __restrict__ Wv, const float* __restrict__ bv,
    const float* __restrict__ Wp)
{
    int idx = blockIdx.x * 256 + threadIdx.x;
    if (idx < 96 * 512) {
        int k = idx >> 9, o = idx & 511;
        g_wt1[idx] = (o < 256) ? Wf[o * 96 + k] : Wv[(o - 256) * 96 + k];
    } else if (idx < 96 * 512 + 512) {
        int o = idx - 96 * 512;
        g_b1[o] = (o < 256) ? bf[o] : bv[o - 256];
    } else if (idx < 96 * 512 + 512 + 256 * 128) {
        int j = idx - (96 * 512 + 512);
        int k = j >> 7, o = j & 127;
        g_wt3[j] = (o < 96) ? Wp[o * 256 + k] : 0.0f;
    }
}

// ---------------- cp.async helpers ----------------
__device__ __forceinline__ void cp16(uint32_t sdst, const float* gsrc) {
    asm volatile("cp.async.cg.shared.global [%0], [%1], 16;" :: "r"(sdst), "l"(gsrc));
}
__device__ __forceinline__ void cp_commit() {
    asm volatile("cp.async.commit_group;" ::: "memory");
}
__device__ __forceinline__ void cp_wait1() {
    asm volatile("cp.async.wait_group 1;" ::: "memory");
}
__device__ __forceinline__ void cp_wait0() {
    asm volatile("cp.async.wait_group 0;" ::: "memory");
}

// ---------------- FFMA2 compute on one 16-k chunk ----------------
template<int NI>
__device__ __forceinline__ void compute_chunk(
    const float* __restrict__ As_, const float* __restrict__ Bs_,
    int tm, int tn, unsigned long long (*acc2)[4])
{
#pragma unroll
    for (int k = 0; k < BKK; k++) {
        const float* ak = As_ + k * BM;
        const float* bk = Bs_ + k * BN;
        float4 a0 = *reinterpret_cast<const float4*>(ak + tm * 4);
        ulonglong2 bq0 = *reinterpret_cast<const ulonglong2*>(bk + tn * 4);
        ulonglong2 bq1 = *reinterpret_cast<const ulonglong2*>(bk + 64 + tn * 4);
        unsigned long long bb4[4] = {bq0.x, bq0.y, bq1.x, bq1.y};
        float av[8];
        av[0] = a0.x; av[1] = a0.y; av[2] = a0.z; av[3] = a0.w;
        if (NI == 8) {
            float4 a1 = *reinterpret_cast<const float4*>(ak + 32 + tm * 4);
            av[4] = a1.x; av[5] = a1.y; av[6] = a1.z; av[7] = a1.w;
        }
#pragma unroll
        for (int i = 0; i < NI; i++) {
            unsigned long long aa;
            asm("mov.b64 %0, {%1, %1};" : "=l"(aa) : "r"(__float_as_uint(av[i])));
#pragma unroll
            for (int j = 0; j < 4; j++) {
                asm("fma.rn.f32x2 %0, %1, %2, %0;"
                    : "+l"(acc2[i][j]) : "l"(aa), "l"(bb4[j]));
            }
        }
    }
}

// ---------------- SGEMM: 64x128x16, cp.async 3-stage pipeline ----------------
// C[z][o][p] = sum_k Wt[k][o] * X[z][k][p] + bias[o]
__global__ __launch_bounds__(128, 4) void gemm_conv(
    const float* __restrict__ Wt, const float* __restrict__ bias,
    const float* __restrict__ X, float* __restrict__ C,
    int O, int K, int P, int Ostride)
{
    __shared__ float As[3][BKK * BM];   // [k][m], already transposed in global
    __shared__ float Bs[3][BKK * BN];   // [k][n]

    const int z = blockIdx.z;
    X += (size_t)z * K * P;
    C += (size_t)z * O * P;
    const int m0 = blockIdx.y * BM;
    const int n0 = blockIdx.x * BN;
    const int tid = threadIdx.x;
    const int tm = tid >> 4;   // 0..7
    const int tn = tid & 15;   // 0..15

    // copy mappings
    const int a_row = tid >> 4;          // 0..7 (+8 for second)  [16 float4/row of 64]
    const int a_c4  = (tid & 15) << 2;
    const int b_row = tid >> 5;          // 0..3 (+4,+8,+12)      [32 float4/row of 128]
    const int b_c4  = (tid & 31) << 2;

    uint32_t sA[3], sB[3];
#pragma unroll
    for (int s = 0; s < 3; s++) {
        sA[s] = (uint32_t)__cvta_generic_to_shared(&As[s][0]);
        sB[s] = (uint32_t)__cvta_generic_to_shared(&Bs[s][0]);
    }

    const bool full_rows = (m0 + BM <= O);
    const int nch = K / BKK;

    unsigned long long acc2[8][4];
#pragma unroll
    for (int i = 0; i < 8; i++)
#pragma unroll
        for (int j = 0; j < 4; j++) acc2[i][j] = 0ull;

    // issue copies for one chunk into stage s
    auto issue = [&](int chk, int s) {
        const int k0 = chk * BKK;
        const float* wa = Wt + (size_t)(k0 + a_row) * Ostride + m0 + a_c4;
        cp16(sA[s] + (uint32_t)((a_row * BM + a_c4) << 2), wa);
        const float* wa2 = Wt + (size_t)(k0 + a_row + 8) * Ostride + m0 + a_c4;
        cp16(sA[s] + (uint32_t)(((a_row + 8) * BM + a_c4) << 2), wa2);
#pragma unroll
        for (int r = 0; r < 4; r++) {
            const float* xb = X + (size_t)(k0 + b_row + r * 4) * P + n0 + b_c4;
            cp16(sB[s] + (uint32_t)(((b_row + r * 4) * BN + b_c4) << 2), xb);
        }
        cp_commit();
    };

    // prologue: stages 0 and 1
    issue(0, 0);
    if (nch > 1) issue(1, 1);

    for (int chk = 0; chk < nch; chk++) {
        if (chk + 1 < nch) cp_wait1(); else cp_wait0();
        __syncthreads();
        if (chk + 2 < nch) issue(chk + 2, (chk + 2) % 3);
        const float* as = As[chk % 3];
        const float* bs = Bs[chk % 3];
        if (full_rows) compute_chunk<8>(as, bs, tm, tn, acc2);
        else           compute_chunk<4>(as, bs, tm, tn, acc2);
        __syncthreads();   // all done with this stage before it is re-filled
    }

    // ---- epilogue: unpack pairs, bias + store ----
#pragma unroll
    for (int half = 0; half < 2; half++) {
#pragma unroll
        for (int i = 0; i < 4; i++) {
            int gr = m0 + half * 32 + tm * 4 + i;
            if (gr >= O) continue;
            float bs_ = bias[gr];
            int ai = half * 4 + i;
            float c[8];
#pragma unroll
            for (int j = 0; j < 4; j++) {
                uint32_t lo, hi;
                asm("mov.b64 {%0, %1}, %2;" : "=r"(lo), "=r"(hi) : "l"(acc2[ai][j]));
                c[j * 2 + 0] = __uint_as_float(lo);
                c[j * 2 + 1] = __uint_as_float(hi);
            }
            float4 v0, v1;
            v0.x = c[0] + bs_; v0.y = c[1] + bs_;
            v0.z = c[2] + bs_; v0.w = c[3] + bs_;
            v1.x = c[4] + bs_; v1.y = c[5] + bs_;
            v1.z = c[6] + bs_; v1.w = c[7] + bs_;
            *reinterpret_cast<float4*>(C + (size_t)gr * P + n0 + tn * 4) = v0;
            *reinterpret_cast<float4*>(C + (size_t)gr * P + n0 + 64 + tn * 4) = v1;
        }
    }
}

// ---------------- cluster kernel: one 128-thread block per region ----------------
__global__ __launch_bounds__(128) void cluster_kernel(
    const float* __restrict__ fv, float* __restrict__ out1,
    const float* __restrict__ alpha_p, const float* __restrict__ beta_p)
{
    const int r  = blockIdx.x;
    const int f2 = r & 7;
    const int f1 = (r >> 3) & 7;
    const int e  = (r >> 6) & 7;
    const int b  = r >> 9;
    const float alpha = alpha_p[0];
    const float beta  = beta_p[0];

    __shared__ float fs[64][33];
    __shared__ float vs[64][33];
    __shared__ float cfn[4][32];
    __shared__ float vcs[4][32];
    __shared__ float aggs[4][32];
    __shared__ float pnorm_s[64];
    __shared__ float simv[64];
    __shared__ int   idxs[64];
    __shared__ float cnt[4];

    const int tid = threadIdx.x;

    const float* fb = fv + ((size_t)b * 512 + e * 32) * 4096 + (f1 * 8) * 64 + f2 * 8;
    const float* vb = fb + (size_t)256 * 4096;

    for (int i = tid; i < 512; i += 128) {
        int ch   = i >> 4;
        int rem  = i & 15;
        int row  = rem >> 1;
        int half = rem & 1;
        int off  = ch * 4096 + row * 64 + half * 4;
        float4 fval = *reinterpret_cast<const float4*>(fb + off);
        float4 vval = *reinterpret_cast<const float4*>(vb + off);
        int pt = row * 8 + half * 4;
        fs[pt + 0][ch] = fval.x; fs[pt + 1][ch] = fval.y;
        fs[pt + 2][ch] = fval.z; fs[pt + 3][ch] = fval.w;
        vs[pt + 0][ch] = vval.x; vs[pt + 1][ch] = vval.y;
        vs[pt + 2][ch] = vval.z; vs[pt + 3][ch] = vval.w;
    }
    if (tid < 4) cnt[tid] = 0.0f;
    __syncthreads();

    {
        int m = tid >> 5;
        int c = tid & 31;
        int wy = (m >> 1) * 4;
        int hx = (m & 1) * 4;
        float cf = -INFINITY, cv = -INFINITY;
#pragma unroll
        for (int dy = 0; dy < 4; dy++)
#pragma unroll
            for (int dx = 0; dx < 4; dx++) {
                int pt = (wy + dy) * 8 + (hx + dx);
                cf = fmaxf(cf, fs[pt][c]);
                cv = fmaxf(cv, vs[pt][c]);
            }
        vcs[m][c] = cv;
        float sq = cf * cf;
#pragma unroll
        for (int o = 16; o > 0; o >>= 1) sq += __shfl_xor_sync(0xffffffffu, sq, o);
        float nrm = fmaxf(sqrtf(sq), 1e-12f);
        cfn[m][c] = cf / nrm;
    }
    if (tid < 64) {
        float sq = 0.0f;
#pragma unroll
        for (int c = 0; c < 32; c++) { float t = fs[tid][c]; sq += t * t; }
        pnorm_s[tid] = fmaxf(sqrtf(sq), 1e-12f);
    }
    __syncthreads();

    if (tid < 64) {
        int n = tid;
        float inv = 1.0f / pnorm_s[n];
        float best = -INFINITY;
        int bi = 0;
#pragma unroll
        for (int m = 0; m < 4; m++) {
            float dot = 0.0f;
#pragma unroll
            for (int c = 0; c < 32; c++) dot += cfn[m][c] * fs[n][c];
            float cosv = dot * inv;
            float s = 1.0f / (1.0f + expf(-(beta + alpha * cosv)));
            if (s > best) { best = s; bi = m; }
        }
        simv[n] = best;
        idxs[n] = bi;
        atomicAdd(&cnt[bi], 1.0f);
    }
    __syncthreads();

    {
        int m = tid >> 5;
        int c = tid & 31;
        float s = vcs[m][c];
        for (int n = 0; n < 64; n++) {
            if (idxs[n] == m) s += vs[n][c] * simv[n];
        }
        aggs[m][c] = s / (cnt[m] + 1.0f);
    }
    __syncthreads();

    if (tid < 64) {
        int n = tid;
        int m = idxs[n];
        float s = simv[n];
#pragma unroll
        for (int c = 0; c < 32; c++) fs[n][c] = aggs[m][c] * s;
    }
    __syncthreads();

    float* ob = out1 + ((size_t)b * 256 + e * 32) * 4096 + (f1 * 8) * 64 + f2 * 8;
    for (int i = tid; i < 512; i += 128) {
        int ch   = i >> 4;
        int rem  = i & 15;
        int row  = rem >> 1;
        int half = rem & 1;
        int pt = row * 8 + half * 4;
        float4 v;
        v.x = fs[pt + 0][ch];
        v.y = fs[pt + 1][ch];
        v.z = fs[pt + 2][ch];
        v.w = fs[pt + 3][ch];
        *reinterpret_cast<float4*>(ob + ch * 4096 + row * 64 + half * 4) = v;
    }
}

// ---------------- launch ----------------
extern "C" void kernel_launch(void* const* d_in, const int* in_sizes, int n_in,
                              void* d_out, int out_size)
{
    const float* x  = (const float*)d_in[0];   // [16,96,64,64]
    const float* Wf = (const float*)d_in[1];   // [256,96]
    const float* bf = (const float*)d_in[2];   // [256]
    const float* Wv = (const float*)d_in[3];   // [256,96]
    const float* bv = (const float*)d_in[4];   // [256]
    const float* Wp = (const float*)d_in[5];   // [96,256]
    const float* bp = (const float*)d_in[6];   // [96]
    const float* sa = (const float*)d_in[7];   // [1]
    const float* sb = (const float*)d_in[8];   // [1]
    float* out = (float*)d_out;                // [16,96,64,64]

    float *fv_ptr, *out1_ptr, *wt1_ptr, *wt3_ptr, *b1_ptr;
    cudaGetSymbolAddress((void**)&fv_ptr,   g_fv);
    cudaGetSymbolAddress((void**)&out1_ptr, g_out1);
    cudaGetSymbolAddress((void**)&wt1_ptr,  g_wt1);
    cudaGetSymbolAddress((void**)&wt3_ptr,  g_wt3);
    cudaGetSymbolAddress((void**)&b1_ptr,   g_b1);

    // 0) prep: transpose weights, concat bias
    prep_weights<<<(96 * 512 + 512 + 256 * 128 + 255) / 256, 256>>>(Wf, bf, Wv, bv, Wp);

    // 1) f & v convs fused: [512 x 4096] per image
    {
        dim3 grid(4096 / BN, 512 / BM, 16);
        gemm_conv<<<grid, 128>>>(wt1_ptr, b1_ptr, x, fv_ptr, 512, 96, 4096, 512);
    }
    // 2) cluster stage: 8192 regions
    cluster_kernel<<<8192, 128>>>(fv_ptr, out1_ptr, sa, sb);
    // 3) final 1x1 conv: [96 x 4096] per image (tile1 skips dead upper half)
    {
        dim3 grid(4096 / BN, 2, 16);
        gemm_conv<<<grid, 128>>>(wt3_ptr, bp, out1_ptr, out, 96, 256, 4096, 128);
    }
}